// round 2
// baseline (speedup 1.0000x reference)
#include <cuda_runtime.h>
#include <cstdint>

#define FHW 32
#define NA 9
#define NBOX (FHW*FHW*NA)   // 9216
#define NW 144              // mask words per sorted row (9216/64)
#define CIN 256
#define COUT 512
#define IMGF 512.0f

// ---------------- scratch (static device globals; no allocation) ----------------
__device__ float  g_h[1024*512];                 // h[pos][och], 2 MB
__device__ float4 g_boxes[NBOX];                 // decoded clipped boxes, original order
__device__ float  g_scores[NBOX];
__device__ unsigned long long g_keys[NBOX];      // sort keys
__device__ int    g_sidx[NBOX];                  // sorted rank -> original index
__device__ float4 g_sboxes[NBOX];                // boxes in sorted order
__device__ unsigned long long g_mask[(size_t)NBOX*NW]; // suppression bitmask (10.6 MB)
__device__ int    g_keep[NBOX];
__device__ int    g_M;                           // number of valid boxes

// anchors: a = s*3 + r ; w = size/sqrt(ratio), h = size*sqrt(ratio)
__constant__ float c_aw[9] = {45.254833995939045f, 32.0f, 22.627416997969522f,
                              90.50966799187809f,  64.0f, 45.254833995939045f,
                              181.01933598375618f, 128.0f, 90.50966799187809f};
__constant__ float c_ah[9] = {22.627416997969522f, 32.0f, 45.254833995939045f,
                              45.254833995939045f, 64.0f, 90.50966799187809f,
                              90.50966799187809f,  128.0f, 181.01933598375618f};

// ---------------- kernel 1: 3x3 conv 256->512 + bias + relu ----------------
// grid (8 spatial tiles, 16 och groups), 128 threads.
// block tile: 32 och x (16x8 positions). thread: 8 och x 4 consecutive x-positions.
__global__ __launch_bounds__(128) void k_conv(const float* __restrict__ x,
                                              const float* __restrict__ w,
                                              const float* __restrict__ b)
{
    __shared__ float xs[16][18][10];                 // [c][col(padded x)][row]  (col-major rows -> conflict-free)
    __shared__ __align__(16) float ws[16][9][32];    // [c][tap][och]

    const int tid = threadIdx.x;
    const int sx = blockIdx.x & 1, sy = blockIdx.x >> 1;
    const int x0 = sx * 16, y0 = sy * 8;
    const int ob = blockIdx.y * 32;
    const int pt = tid & 31, ot = tid >> 5;
    const int cg = pt & 3, pr = pt >> 2;

    if (blockIdx.x == 0 && blockIdx.y == 0 && tid == 0) g_M = 0;

    float acc[8][4];
    #pragma unroll
    for (int o = 0; o < 8; o++)
        #pragma unroll
        for (int i = 0; i < 4; i++) acc[o][i] = 0.0f;

    for (int c0 = 0; c0 < CIN; c0 += 16) {
        __syncthreads();
        // load input patch: 16ch x 18cols x 10rows
        for (int t = tid; t < 16*18*10; t += 128) {
            int c = t / 180, r2 = t % 180, col = r2 / 10, row = r2 % 10;
            int gx = x0 + col - 1, gy = y0 + row - 1;
            float v = 0.0f;
            if ((unsigned)gx < 32u && (unsigned)gy < 32u)
                v = x[(c0 + c) * 1024 + gy * 32 + gx];
            xs[c][col][row] = v;
        }
        // load weights: 32 och x 16ch x 9 taps (coalesced along c,tap)
        for (int t = tid; t < 16*9*32; t += 128) {
            int o = t / 144, r2 = t % 144, c = r2 / 9, tap = r2 % 9;
            ws[c][tap][o] = w[(size_t)(ob + o) * 2304 + (c0 + c) * 9 + tap];
        }
        __syncthreads();

        for (int c = 0; c < 16; c++) {
            #pragma unroll
            for (int dy = 0; dy < 3; dy++) {
                #pragma unroll
                for (int dx = 0; dx < 3; dx++) {
                    const float* wp = &ws[c][dy*3+dx][ot*8];
                    float4 wa = *(const float4*)wp;
                    float4 wb = *(const float4*)(wp + 4);
                    float wv[8] = {wa.x, wa.y, wa.z, wa.w, wb.x, wb.y, wb.z, wb.w};
                    float xv0 = xs[c][cg*4+0+dx][pr+dy];
                    float xv1 = xs[c][cg*4+1+dx][pr+dy];
                    float xv2 = xs[c][cg*4+2+dx][pr+dy];
                    float xv3 = xs[c][cg*4+3+dx][pr+dy];
                    #pragma unroll
                    for (int o = 0; o < 8; o++) {
                        acc[o][0] += wv[o] * xv0;
                        acc[o][1] += wv[o] * xv1;
                        acc[o][2] += wv[o] * xv2;
                        acc[o][3] += wv[o] * xv3;
                    }
                }
            }
        }
    }

    float bias[8];
    #pragma unroll
    for (int o = 0; o < 8; o++) bias[o] = b[ob + ot*8 + o];

    const int px = x0 + cg * 4, py = y0 + pr;
    #pragma unroll
    for (int i = 0; i < 4; i++) {
        int p = py * 32 + px + i;
        float4 v0, v1;
        v0.x = fmaxf(acc[0][i] + bias[0], 0.0f);
        v0.y = fmaxf(acc[1][i] + bias[1], 0.0f);
        v0.z = fmaxf(acc[2][i] + bias[2], 0.0f);
        v0.w = fmaxf(acc[3][i] + bias[3], 0.0f);
        v1.x = fmaxf(acc[4][i] + bias[4], 0.0f);
        v1.y = fmaxf(acc[5][i] + bias[5], 0.0f);
        v1.z = fmaxf(acc[6][i] + bias[6], 0.0f);
        v1.w = fmaxf(acc[7][i] + bias[7], 0.0f);
        float* hp = &g_h[(size_t)p * 512 + ob + ot*8];
        *(float4*)hp       = v0;
        *(float4*)(hp + 4) = v1;
    }
}

// ---------------- kernel 2: heads (scores + offsets), decode, valid, keys ----------------
// one block per spatial position, 128 threads
__global__ __launch_bounds__(128) void k_heads(const float* __restrict__ w2, const float* __restrict__ b2,
                                               const float* __restrict__ w3, const float* __restrict__ b3)
{
    __shared__ __align__(16) float hs[512];
    __shared__ float outv[45];
    const int p = blockIdx.x;
    const int tid = threadIdx.x;
    ((float4*)hs)[tid] = ((const float4*)(g_h + (size_t)p * 512))[tid];
    __syncthreads();

    const int wrp = tid >> 5, lane = tid & 31;
    for (int o = wrp; o < 45; o += 4) {
        const float* wr; float bb;
        if (o < 9) { wr = w2 + o * 512;       bb = b2[o];     }
        else       { wr = w3 + (o - 9) * 512; bb = b3[o - 9]; }
        float s = 0.0f;
        #pragma unroll 4
        for (int c = lane; c < 512; c += 32) s += hs[c] * wr[c];
        #pragma unroll
        for (int off = 16; off; off >>= 1) s += __shfl_down_sync(0xffffffffu, s, off);
        if (lane == 0) outv[o] = s + bb;
    }
    __syncthreads();

    if (tid < 9) {
        const int a = tid;
        const int y = p >> 5, xx = p & 31;
        float logit = outv[a];
        float score = 1.0f / (1.0f + expf(-logit));
        float t0 = outv[9 + a*4 + 0], t1 = outv[9 + a*4 + 1];
        float t2 = outv[9 + a*4 + 2], t3 = outv[9 + a*4 + 3];
        float aw = c_aw[a], ah = c_ah[a];
        float acx = (xx + 0.5f) * 16.0f, acy = (y + 0.5f) * 16.0f;
        float cx = acx + t0 * aw, cy = acy + t1 * ah;
        float bw = aw * expf(t2), bh = ah * expf(t3);
        float x1 = cx - bw * 0.5f, y1 = cy - bh * 0.5f;
        float x2 = cx + bw * 0.5f, y2 = cy + bh * 0.5f;
        x1 = fminf(fmaxf(x1, 0.0f), IMGF); y1 = fminf(fmaxf(y1, 0.0f), IMGF);
        x2 = fminf(fmaxf(x2, 0.0f), IMGF); y2 = fminf(fmaxf(y2, 0.0f), IMGF);
        bool valid = (x2 - x1 >= 0.001f) && (y2 - y1 >= 0.001f) && (score >= 0.5f);
        int n = p * 9 + a;
        g_scores[n] = score;
        g_boxes[n] = make_float4(x1, y1, x2, y2);
        unsigned long long key;
        if (valid) {
            key = ((unsigned long long)__float_as_uint(score) << 32)
                | (unsigned long long)(0xFFFFFFFFu - (unsigned)n);
            atomicAdd(&g_M, 1);
        } else {
            key = (unsigned long long)(0xFFFFFFFFu - (unsigned)n); // unique, below any valid key
        }
        g_keys[n] = key;
    }
}

// ---------------- kernel 3: exact stable descending sort via enumeration ranking ----------------
__global__ __launch_bounds__(256) void k_rank()
{
    __shared__ unsigned long long ks[2304];
    const int i = blockIdx.x * 256 + threadIdx.x;
    const unsigned long long mykey = g_keys[i];
    g_keep[i] = 0;                       // reset keep flags for this replay
    int cnt = 0;
    for (int t0 = 0; t0 < NBOX; t0 += 2304) {
        __syncthreads();
        for (int t = threadIdx.x; t < 2304; t += 256) ks[t] = g_keys[t0 + t];
        __syncthreads();
        #pragma unroll 8
        for (int j = 0; j < 2304; j++) cnt += (ks[j] > mykey) ? 1 : 0;
    }
    g_sidx[cnt] = i;                     // keys are unique -> cnt is a permutation
    g_sboxes[cnt] = g_boxes[i];
}

// ---------------- kernel 4: pairwise suppression bitmask (sorted order, upper triangle) ----------------
__global__ __launch_bounds__(64) void k_mask()
{
    const int rb = blockIdx.y, cb = blockIdx.x;
    if (cb < rb) return;
    const int M = g_M;
    if (rb * 64 >= M) return;

    __shared__ float4 cboxes[64];
    const int tid = threadIdx.x;
    const int j0 = cb * 64;
    cboxes[tid] = g_sboxes[j0 + tid];
    __syncthreads();

    const int r = rb * 64 + tid;
    if (r >= M) return;
    const float4 mb = g_sboxes[r];
    const float myarea = (mb.z - mb.x) * (mb.w - mb.y);
    unsigned long long word = 0ull;
    #pragma unroll 4
    for (int jj = 0; jj < 64; jj++) {
        int j = j0 + jj;
        float4 obx = cboxes[jj];
        float area2 = (obx.z - obx.x) * (obx.w - obx.y);
        float ix1 = fmaxf(mb.x, obx.x), iy1 = fmaxf(mb.y, obx.y);
        float ix2 = fminf(mb.z, obx.z), iy2 = fminf(mb.w, obx.w);
        float inter = fmaxf(ix2 - ix1, 0.0f) * fmaxf(iy2 - iy1, 0.0f);
        float uni = myarea + area2 - inter;
        float iou = inter / fmaxf(uni, 1e-9f);
        if (j > r && j < M && iou > 0.7f) word |= (1ull << jj);
    }
    g_mask[(size_t)r * NW + cb] = word;
}

// ---------------- kernel 5: batched greedy scan ----------------
// per 64-row batch: thread0 runs the in-register sequential closure, then the
// block eagerly ORs kept rows' remaining mask words into smem remv.
__global__ __launch_bounds__(128) void k_scan()
{
    __shared__ unsigned long long remv[NW];
    __shared__ unsigned long long selfw[64];
    __shared__ unsigned long long kb_s;
    const int tid = threadIdx.x;
    const int M = g_M;
    const int nwords = (M + 63) >> 6;
    for (int t = tid; t < NW; t += 128) remv[t] = 0ull;
    __syncthreads();

    for (int w = 0; w < nwords; w++) {
        const int rbase = w << 6;
        const int cnt = min(64, M - rbase);
        if (tid < 64) selfw[tid] = (tid < cnt) ? g_mask[(size_t)(rbase + tid) * NW + w] : 0ull;
        __syncthreads();
        if (tid == 0) {
            unsigned long long cur = remv[w];
            unsigned long long kb = 0ull;
            #pragma unroll
            for (int rr = 0; rr < 64; rr++) {
                unsigned long long take = ((cur >> rr) & 1ull) ^ 1ull;
                kb |= take << rr;
                cur |= take ? selfw[rr] : 0ull;
            }
            if (cnt < 64) kb &= (1ull << cnt) - 1ull;
            kb_s = kb;
        }
        __syncthreads();
        const unsigned long long kb = kb_s;
        if (tid < cnt && ((kb >> tid) & 1ull))
            g_keep[g_sidx[rbase + tid]] = 1;
        for (int w2 = w + 1 + tid; w2 < nwords; w2 += 128) {
            unsigned long long accw = remv[w2];
            unsigned long long t = kb;
            while (t) {
                int rr = __ffsll((long long)t) - 1;
                t &= t - 1ull;
                accw |= g_mask[(size_t)(rbase + rr) * NW + w2];
            }
            remv[w2] = accw;
        }
        __syncthreads();
    }
}

// ---------------- kernel 6: write output (N,5) ----------------
__global__ __launch_bounds__(256) void k_out(float* __restrict__ out)
{
    const int n = blockIdx.x * 256 + threadIdx.x;
    float m = g_keep[n] ? 1.0f : 0.0f;
    float4 bx = g_boxes[n];
    float s = g_scores[n];
    float* o = out + (size_t)n * 5;
    o[0] = bx.x * m; o[1] = bx.y * m; o[2] = bx.z * m; o[3] = bx.w * m; o[4] = s * m;
}

// ---------------- launch ----------------
extern "C" void kernel_launch(void* const* d_in, const int* in_sizes, int n_in,
                              void* d_out, int out_size)
{
    const float* fm = (const float*)d_in[0];
    const float* w1 = (const float*)d_in[1];
    const float* b1 = (const float*)d_in[2];
    const float* w2 = (const float*)d_in[3];
    const float* b2 = (const float*)d_in[4];
    const float* w3 = (const float*)d_in[5];
    const float* b3 = (const float*)d_in[6];

    k_conv <<<dim3(8, 16), 128>>>(fm, w1, b1);
    k_heads<<<1024, 128>>>(w2, b2, w3, b3);
    k_rank <<<36, 256>>>();
    k_mask <<<dim3(144, 144), 64>>>();
    k_scan <<<1, 128>>>();
    k_out  <<<36, 256>>>((float*)d_out);
}

// round 3
// speedup vs baseline: 1.1037x; 1.1037x over previous
#include <cuda_runtime.h>
#include <cstdint>

typedef unsigned long long ull;

#define FHW 32
#define NA 9
#define NBOX (FHW*FHW*NA)   // 9216
#define NW 144              // mask words per sorted row (9216/64)
#define CIN 256
#define IMGF 512.0f

// ---------------- scratch ----------------
__device__ float  g_h[1024*512];                 // h[pos][och], 2 MB
__device__ float4 g_boxes[NBOX];
__device__ float  g_scores[NBOX];
__device__ ull    g_keys[NBOX];
__device__ int    g_sidx[NBOX];
__device__ float4 g_sboxes[NBOX];
__device__ ull    g_mask[(size_t)NBOX*NW];       // 10.6 MB
__device__ int    g_keep[NBOX];
__device__ int    g_M;

__constant__ float c_aw[9] = {45.254833995939045f, 32.0f, 22.627416997969522f,
                              90.50966799187809f,  64.0f, 45.254833995939045f,
                              181.01933598375618f, 128.0f, 90.50966799187809f};
__constant__ float c_ah[9] = {22.627416997969522f, 32.0f, 45.254833995939045f,
                              45.254833995939045f, 64.0f, 90.50966799187809f,
                              90.50966799187809f,  128.0f, 181.01933598375618f};

// packed dual-fp32 FMA (Blackwell): acc = a*b + acc, per 32-bit lane
#define FMA2(acc, a, b) asm("fma.rn.f32x2 %0, %1, %2, %0;" : "+l"(acc) : "l"(a), "l"(b))

// ---------------- kernel 1: 3x3 conv 256->512 + bias + relu (f32x2) ----------------
// grid (8 spatial tiles of 16x8, 16 och groups of 32), 128 threads.
// thread: 8 och (4 f32x2 pairs) x 4 consecutive x-positions.
__global__ __launch_bounds__(128) void k_conv(const float* __restrict__ x,
                                              const float* __restrict__ w,
                                              const float* __restrict__ b)
{
    __shared__ ull   xs2[16][18][10];     // [c][col][row], value packed {x,x}; 23 KB
    __shared__ float ws[4896];            // [(c*9+tap)*34 + och], stride 34 (conflict-free, 8B-aligned pairs)

    const int tid = threadIdx.x;
    const int sx = blockIdx.x & 1, sy = blockIdx.x >> 1;
    const int x0 = sx * 16, y0 = sy * 8;
    const int ob = blockIdx.y * 32;
    const int pt = tid & 31, ot = tid >> 5;
    const int cg = pt & 3, pr = pt >> 2;
    const int cg4 = cg * 4, ot8 = ot * 8;

    if (blockIdx.x == 0 && blockIdx.y == 0 && tid == 0) g_M = 0;

    ull acc2[4][4];                       // [och pair][pos]
    #pragma unroll
    for (int o = 0; o < 4; o++)
        #pragma unroll
        for (int i = 0; i < 4; i++) acc2[o][i] = 0ull;

    for (int c0 = 0; c0 < CIN; c0 += 16) {
        __syncthreads();
        // input patch: 16ch x 18cols x 10rows, duplicated-packed
        for (int t = tid; t < 16*18*10; t += 128) {
            int c = t / 180, r2 = t - c*180, col = r2 / 10, row = r2 - col*10;
            int gx = x0 + col - 1, gy = y0 + row - 1;
            float v = 0.0f;
            if ((unsigned)gx < 32u && (unsigned)gy < 32u)
                v = x[(c0 + c) * 1024 + gy * 32 + gx];
            unsigned xb = __float_as_uint(v);
            ull pv; asm("mov.b64 %0, {%1, %1};" : "=l"(pv) : "r"(xb));
            xs2[c][col][row] = pv;
        }
        // weights: coalesced read, conflict-free strided store
        {
            int o = 0, rr = tid;          // tid < 128 < 144
            #pragma unroll 4
            for (int k = 0; k < 36; k++) {
                ws[rr * 34 + o] = w[(size_t)(ob + o) * 2304 + c0 * 9 + rr];
                rr += 128; if (rr >= 144) { rr -= 144; o++; }
            }
        }
        __syncthreads();

        for (int c = 0; c < 16; c++) {
            #pragma unroll
            for (int dy = 0; dy < 3; dy++) {
                ull xv[6];
                #pragma unroll
                for (int q = 0; q < 6; q++) xv[q] = xs2[c][cg4 + q][pr + dy];
                #pragma unroll
                for (int dx = 0; dx < 3; dx++) {
                    const ull* wp = (const ull*)&ws[(c*9 + dy*3 + dx) * 34 + ot8];
                    ull w0 = wp[0], w1 = wp[1], w2v = wp[2], w3v = wp[3];
                    #pragma unroll
                    for (int i = 0; i < 4; i++) {
                        ull xp = xv[i + dx];
                        FMA2(acc2[0][i], w0,  xp);
                        FMA2(acc2[1][i], w1,  xp);
                        FMA2(acc2[2][i], w2v, xp);
                        FMA2(acc2[3][i], w3v, xp);
                    }
                }
            }
        }
    }

    float bias[8];
    #pragma unroll
    for (int o = 0; o < 8; o++) bias[o] = b[ob + ot8 + o];

    const int px = x0 + cg4, py = y0 + pr;
    #pragma unroll
    for (int i = 0; i < 4; i++) {
        int p = py * 32 + px + i;
        float r[8];
        #pragma unroll
        for (int op = 0; op < 4; op++) {
            ull v = acc2[op][i];
            r[2*op]   = __uint_as_float((unsigned)v);
            r[2*op+1] = __uint_as_float((unsigned)(v >> 32));
        }
        float4 v0, v1;
        v0.x = fmaxf(r[0] + bias[0], 0.0f); v0.y = fmaxf(r[1] + bias[1], 0.0f);
        v0.z = fmaxf(r[2] + bias[2], 0.0f); v0.w = fmaxf(r[3] + bias[3], 0.0f);
        v1.x = fmaxf(r[4] + bias[4], 0.0f); v1.y = fmaxf(r[5] + bias[5], 0.0f);
        v1.z = fmaxf(r[6] + bias[6], 0.0f); v1.w = fmaxf(r[7] + bias[7], 0.0f);
        float* hp = &g_h[(size_t)p * 512 + ob + ot8];
        *(float4*)hp       = v0;
        *(float4*)(hp + 4) = v1;
    }
}

// ---------------- kernel 2: heads, decode, valid, keys ----------------
__global__ __launch_bounds__(128) void k_heads(const float* __restrict__ w2, const float* __restrict__ b2,
                                               const float* __restrict__ w3, const float* __restrict__ b3)
{
    __shared__ __align__(16) float hs[512];
    __shared__ float outv[45];
    const int p = blockIdx.x;
    const int tid = threadIdx.x;
    if (tid < 9) g_keep[p * 9 + tid] = 0;     // reset keep flags for this replay
    ((float4*)hs)[tid] = ((const float4*)(g_h + (size_t)p * 512))[tid];
    __syncthreads();

    const int wrp = tid >> 5, lane = tid & 31;
    for (int o = wrp; o < 45; o += 4) {
        const float* wr; float bb;
        if (o < 9) { wr = w2 + o * 512;       bb = b2[o];     }
        else       { wr = w3 + (o - 9) * 512; bb = b3[o - 9]; }
        float s = 0.0f;
        #pragma unroll 8
        for (int c = lane; c < 512; c += 32) s += hs[c] * wr[c];
        #pragma unroll
        for (int off = 16; off; off >>= 1) s += __shfl_down_sync(0xffffffffu, s, off);
        if (lane == 0) outv[o] = s + bb;
    }
    __syncthreads();

    if (tid < 9) {
        const int a = tid;
        const int y = p >> 5, xx = p & 31;
        float score = 1.0f / (1.0f + expf(-outv[a]));
        float t0 = outv[9 + a*4 + 0], t1 = outv[9 + a*4 + 1];
        float t2 = outv[9 + a*4 + 2], t3 = outv[9 + a*4 + 3];
        float aw = c_aw[a], ah = c_ah[a];
        float acx = (xx + 0.5f) * 16.0f, acy = (y + 0.5f) * 16.0f;
        float cx = acx + t0 * aw, cy = acy + t1 * ah;
        float bw = aw * expf(t2), bh = ah * expf(t3);
        float x1 = cx - bw * 0.5f, y1 = cy - bh * 0.5f;
        float x2 = cx + bw * 0.5f, y2 = cy + bh * 0.5f;
        x1 = fminf(fmaxf(x1, 0.0f), IMGF); y1 = fminf(fmaxf(y1, 0.0f), IMGF);
        x2 = fminf(fmaxf(x2, 0.0f), IMGF); y2 = fminf(fmaxf(y2, 0.0f), IMGF);
        bool valid = (x2 - x1 >= 0.001f) && (y2 - y1 >= 0.001f) && (score >= 0.5f);
        int n = p * 9 + a;
        g_scores[n] = score;
        g_boxes[n] = make_float4(x1, y1, x2, y2);
        ull key;
        if (valid) {
            key = ((ull)__float_as_uint(score) << 32)
                | (ull)(0xFFFFFFFFu - (unsigned)n);
            atomicAdd(&g_M, 1);
        } else {
            key = (ull)(0xFFFFFFFFu - (unsigned)n);
        }
        g_keys[n] = key;
    }
}

// ---------------- kernel 3: exact stable descending argsort via enumeration ranking ----------------
// 8 threads per key, interleaved sub-slices; shfl-reduce partial counts.
__global__ __launch_bounds__(256) void k_rank()
{
    __shared__ ull ks[1024];
    const int tid = threadIdx.x;
    const int kl = tid >> 3, sub = tid & 7;
    const int i = blockIdx.x * 32 + kl;
    const ull mykey = g_keys[i];
    int cnt = 0;
    for (int t0 = 0; t0 < NBOX; t0 += 1024) {
        __syncthreads();
        #pragma unroll
        for (int t = tid; t < 1024; t += 256) ks[t] = g_keys[t0 + t];
        __syncthreads();
        #pragma unroll 8
        for (int t = 0; t < 128; t++) cnt += (ks[t * 8 + sub] > mykey) ? 1 : 0;
    }
    cnt += __shfl_down_sync(0xffffffffu, cnt, 4, 8);
    cnt += __shfl_down_sync(0xffffffffu, cnt, 2, 8);
    cnt += __shfl_down_sync(0xffffffffu, cnt, 1, 8);
    if (sub == 0) {
        g_sidx[cnt] = i;       // unique keys -> cnt is a permutation
        g_sboxes[cnt] = g_boxes[i];
    }
}

// ---------------- kernel 4: suppression bitmask ----------------
// block = 128 rows x 1 column word; grid (cw=144, rp=72); precomputed allow mask.
__global__ __launch_bounds__(128) void k_mask()
{
    const int cw = blockIdx.x;
    const int rp = blockIdx.y;
    const int M = g_M;
    if (rp * 128 >= M) return;
    if (cw * 64 >= M) return;
    if (cw < 2 * rp) return;

    __shared__ float4 cb[64];
    __shared__ float  carea[64];
    const int tid = threadIdx.x;
    if (tid < 64) {
        float4 bb = g_sboxes[cw * 64 + tid];
        cb[tid] = bb;
        carea[tid] = (bb.z - bb.x) * (bb.w - bb.y);
    }
    __syncthreads();

    const int r = rp * 128 + tid;
    const int d = r - cw * 64;
    if (r >= M || d > 63) return;

    ull allow = ~0ull;
    if (d >= 0) allow = (d >= 63) ? 0ull : (~0ull << (d + 1));
    int rem = M - cw * 64;
    if (rem < 64) allow &= ((1ull << rem) - 1ull);

    ull word = 0ull;
    if (allow) {
        float4 mb = g_sboxes[r];
        float ma = (mb.z - mb.x) * (mb.w - mb.y);
        unsigned lo = 0, hi = 0;
        #pragma unroll
        for (int jj = 0; jj < 32; jj++) {
            float4 ob = cb[jj];
            float ix1 = fmaxf(mb.x, ob.x), iy1 = fmaxf(mb.y, ob.y);
            float ix2 = fminf(mb.z, ob.z), iy2 = fminf(mb.w, ob.w);
            float inter = fmaxf(ix2 - ix1, 0.0f) * fmaxf(iy2 - iy1, 0.0f);
            float uni = ma + carea[jj] - inter;
            float iou = inter / fmaxf(uni, 1e-9f);
            if (iou > 0.7f) lo |= (1u << jj);
        }
        #pragma unroll
        for (int jj = 0; jj < 32; jj++) {
            float4 ob = cb[32 + jj];
            float ix1 = fmaxf(mb.x, ob.x), iy1 = fmaxf(mb.y, ob.y);
            float ix2 = fminf(mb.z, ob.z), iy2 = fminf(mb.w, ob.w);
            float inter = fmaxf(ix2 - ix1, 0.0f) * fmaxf(iy2 - iy1, 0.0f);
            float uni = ma + carea[32 + jj] - inter;
            float iou = inter / fmaxf(uni, 1e-9f);
            if (iou > 0.7f) hi |= (1u << jj);
        }
        word = (((ull)hi << 32) | lo) & allow;
    }
    g_mask[(size_t)r * NW + cw] = word;
}

// ---------------- kernel 5: batched greedy scan (with selfw prefetch) ----------------
__global__ __launch_bounds__(128) void k_scan()
{
    __shared__ ull remv[NW];
    __shared__ ull selfw[64];
    __shared__ ull kb_s;
    const int tid = threadIdx.x;
    const int M = g_M;
    const int nwords = (M + 63) >> 6;
    for (int t = tid; t < NW; t += 128) remv[t] = 0ull;

    ull nxt = 0ull;
    if (tid < 64 && tid < M && nwords > 0)
        nxt = g_mask[(size_t)tid * NW + 0];
    __syncthreads();

    for (int w = 0; w < nwords; w++) {
        const int rbase = w << 6;
        const int cnt = min(64, M - rbase);
        if (tid < 64) selfw[tid] = nxt;
        __syncthreads();
        // prefetch next word's diagonal rows while thread0 runs the closure
        if (tid < 64) {
            int rr2 = rbase + 64 + tid;
            nxt = (w + 1 < nwords && rr2 < M)
                ? g_mask[(size_t)rr2 * NW + (w + 1)] : 0ull;
        }
        if (tid == 0) {
            ull cur = remv[w];
            ull kb = 0ull;
            #pragma unroll
            for (int rr = 0; rr < 64; rr++) {
                ull take = ((cur >> rr) & 1ull) ^ 1ull;
                kb |= take << rr;
                cur |= take ? selfw[rr] : 0ull;
            }
            if (cnt < 64) kb &= (1ull << cnt) - 1ull;
            kb_s = kb;
        }
        __syncthreads();
        const ull kb = kb_s;
        if (tid < cnt && ((kb >> tid) & 1ull))
            g_keep[g_sidx[rbase + tid]] = 1;
        for (int w2 = w + 1 + tid; w2 < nwords; w2 += 128) {
            ull accw = remv[w2];
            ull t = kb;
            while (t) {
                int rr = __ffsll((long long)t) - 1;
                t &= t - 1ull;
                accw |= g_mask[(size_t)(rbase + rr) * NW + w2];
            }
            remv[w2] = accw;
        }
        __syncthreads();
    }
}

// ---------------- kernel 6: write output ----------------
__global__ __launch_bounds__(256) void k_out(float* __restrict__ out)
{
    const int n = blockIdx.x * 256 + threadIdx.x;
    float m = g_keep[n] ? 1.0f : 0.0f;
    float4 bx = g_boxes[n];
    float s = g_scores[n];
    float* o = out + (size_t)n * 5;
    o[0] = bx.x * m; o[1] = bx.y * m; o[2] = bx.z * m; o[3] = bx.w * m; o[4] = s * m;
}

// ---------------- launch ----------------
extern "C" void kernel_launch(void* const* d_in, const int* in_sizes, int n_in,
                              void* d_out, int out_size)
{
    const float* fm = (const float*)d_in[0];
    const float* w1 = (const float*)d_in[1];
    const float* b1 = (const float*)d_in[2];
    const float* w2 = (const float*)d_in[3];
    const float* b2 = (const float*)d_in[4];
    const float* w3 = (const float*)d_in[5];
    const float* b3 = (const float*)d_in[6];

    k_conv <<<dim3(8, 16), 128>>>(fm, w1, b1);
    k_heads<<<1024, 128>>>(w2, b2, w3, b3);
    k_rank <<<288, 256>>>();
    k_mask <<<dim3(144, 72), 128>>>();
    k_scan <<<1, 128>>>();
    k_out  <<<36, 256>>>((float*)d_out);
}